// round 16
// baseline (speedup 1.0000x reference)
#include <cuda_runtime.h>
#include <cuda_bf16.h>
#include <math.h>
#include <stdint.h>

#define BV 256
#define LVTOK 196
#define BT 256
#define LT 64
#define DIMC 512
#define HID 102
#define KP 39
#define NK 19
#define L40 40
#define EPSF 1e-12f
#define BIGNEG 1e10f

// ---------------- static device scratch (no allocations) ----------------
__device__ float g_xln[(size_t)BV * LVTOK * DIMC];     // tf32-rounded LN output
__device__ float g_W1r[512 * 104];                     // W1 [k][n], tf32-rounded, padded
__device__ float g_logits[BV * KP * LVTOK];
__device__ float g_aggr[(size_t)BV * KP * DIMC];
__device__ float g_imgrows[(size_t)BV * L40 * DIMC];
__device__ __nv_bfloat16 g_imgrows_bf[(size_t)BV * L40 * DIMC];
__device__ __nv_bfloat16 g_capn_bf[(size_t)BT * LT * DIMC];
__device__ float g_r[BV * KP];
__device__ float g_attself[BV * KP];
__device__ float g_G[(size_t)BV * KP * KP];
__device__ float g_capglo[BT * DIMC];
__device__ float g_c[(size_t)BT * BV * 40];
__device__ unsigned long long g_selmask[BT * BV];

// ---------------- helpers ----------------
__device__ __forceinline__ uint32_t smem_u32(const void* p) {
    uint32_t a;
    asm("{ .reg .u64 t; cvta.to.shared.u64 t, %1; cvt.u32.u64 %0, t; }" : "=r"(a) : "l"(p));
    return a;
}
__device__ __forceinline__ void cpa16(uint32_t dst, const void* src) {
    asm volatile("cp.async.cg.shared.global [%0], [%1], 16;" :: "r"(dst), "l"(src));
}
__device__ __forceinline__ void ldsm_x4(uint32_t& r0, uint32_t& r1, uint32_t& r2, uint32_t& r3,
                                        uint32_t addr) {
    asm volatile("ldmatrix.sync.aligned.m8n8.x4.shared.b16 {%0,%1,%2,%3}, [%4];"
                 : "=r"(r0), "=r"(r1), "=r"(r2), "=r"(r3) : "r"(addr));
}
__device__ __forceinline__ float lds_f(uint32_t addr) {
    float v;
    asm volatile("ld.shared.f32 %0, [%1];" : "=f"(v) : "r"(addr));
    return v;
}
__device__ __forceinline__ float f2tf32(float x) {
    uint32_t o;
    asm("cvt.rna.tf32.f32 %0, %1;" : "=r"(o) : "f"(x));
    return __uint_as_float(o);
}
#define MMA_BF16(C, A0, A1, A2, A3, B0, B1) \
    asm volatile("mma.sync.aligned.m16n8k16.row.col.f32.bf16.bf16.f32 " \
        "{%0,%1,%2,%3}, {%4,%5,%6,%7}, {%8,%9}, {%0,%1,%2,%3};" \
        : "+f"((C)[0]), "+f"((C)[1]), "+f"((C)[2]), "+f"((C)[3]) \
        : "r"(A0), "r"(A1), "r"(A2), "r"(A3), "r"(B0), "r"(B1))
#define MMA_TF32(C, A0, A1, A2, A3, B0, B1) \
    asm volatile("mma.sync.aligned.m16n8k8.row.col.f32.tf32.tf32.f32 " \
        "{%0,%1,%2,%3}, {%4,%5,%6,%7}, {%8,%9}, {%0,%1,%2,%3};" \
        : "+f"((C)[0]), "+f"((C)[1]), "+f"((C)[2]), "+f"((C)[3]) \
        : "r"(A0), "r"(A1), "r"(A2), "r"(A3), "r"(B0), "r"(B1))

// ---------------- K1a: LN -> g_xln (tf32) + W1 prep (grid-stitched) [unchanged] ----------------
__global__ __launch_bounds__(256) void k1a_ln(const float* __restrict__ img,
                                              const float* __restrict__ lng,
                                              const float* __restrict__ lnb,
                                              const float* __restrict__ W1) {
    if (blockIdx.x < 6272) {
        __shared__ __align__(16) float gsh[DIMC], bsh[DIMC];
        int tid = threadIdx.x, wid = tid >> 5, lane = tid & 31;
        for (int d = tid; d < DIMC; d += 256) { gsh[d] = lng[d]; bsh[d] = lnb[d]; }
        __syncthreads();
        int token = blockIdx.x * 8 + wid;
        int b = token / LVTOK, l = token - b * LVTOK;
        const float4* x4 = (const float4*)(img + ((size_t)(b * 197) + 1 + l) * DIMC);
        float4 xv[4]; float s = 0.f, ss = 0.f;
        #pragma unroll
        for (int e = 0; e < 4; ++e) {
            float4 v = x4[lane + 32 * e]; xv[e] = v;
            s += v.x + v.y + v.z + v.w;
            ss += v.x * v.x + v.y * v.y + v.z * v.z + v.w * v.w;
        }
        #pragma unroll
        for (int o = 16; o; o >>= 1) {
            s  += __shfl_xor_sync(0xffffffffu, s, o);
            ss += __shfl_xor_sync(0xffffffffu, ss, o);
        }
        float mu = s * (1.0f / DIMC);
        float rstd = rsqrtf(ss * (1.0f / DIMC) - mu * mu + 1e-5f);
        float4* xd = (float4*)(g_xln + (size_t)token * DIMC);
        #pragma unroll
        for (int e = 0; e < 4; ++e) {
            int i4 = lane + 32 * e;
            float4 g4 = ((const float4*)gsh)[i4];
            float4 b4 = ((const float4*)bsh)[i4];
            float4 o4;
            o4.x = f2tf32((xv[e].x - mu) * rstd * g4.x + b4.x);
            o4.y = f2tf32((xv[e].y - mu) * rstd * g4.y + b4.y);
            o4.z = f2tf32((xv[e].z - mu) * rstd * g4.z + b4.z);
            o4.w = f2tf32((xv[e].w - mu) * rstd * g4.w + b4.w);
            xd[i4] = o4;
        }
    } else {
        int base = (blockIdx.x - 6272) * 1024 + threadIdx.x * 4;
        #pragma unroll
        for (int u = 0; u < 4; ++u) {
            int idx = base + u;
            if (idx < 512 * 104) {
                int k = idx / 104, n = idx - k * 104;
                g_W1r[idx] = (n < HID) ? f2tf32(W1[k * HID + n]) : 0.f;
            }
        }
    }
}

// ---------------- K1b: tf32 mma GEMM1 + gelu + fp32 GEMM2 -> logits [unchanged] ----------------
#define XKS 68
#define BKS 104
#define XS_BYTES (32 * XKS * 4)
#define BS_BYTES (64 * BKS * 4)
#define O_XS0 0
#define O_XS1 (O_XS0 + XS_BYTES)
#define O_BS0 (O_XS1 + XS_BYTES)
#define O_BS1 (O_BS0 + BS_BYTES)
#define O_H2  (O_BS1 + BS_BYTES)
#define O_W2  (O_H2 + 32 * 104 * 4)
#define O_B1  (O_W2 + HID * 40 * 4)
#define K1B_DYN (O_B1 + 104 * 4)

__global__ __launch_bounds__(256) void k1b_mlp(const float* __restrict__ W2,
                                               const float* __restrict__ b1,
                                               const float* __restrict__ b2,
                                               const float* __restrict__ scale) {
    extern __shared__ char dsm[];
    uint32_t sb = smem_u32(dsm);
    float* h2s = (float*)(dsm + O_H2);
    float* W2s = (float*)(dsm + O_W2);
    float* b1s = (float*)(dsm + O_B1);
    int tid = threadIdx.x, wp = tid >> 5, lane = tid & 31;
    int token0 = blockIdx.x * 32;

    for (int idx = tid; idx < HID * KP; idx += 256) {
        int j = idx / KP, l = idx - j * KP;
        W2s[j * 40 + l] = W2[idx];
    }
    if (tid < 104) b1s[tid] = (tid < HID) ? b1[tid] : 0.f;

#define K1B_ISSUE(CH) do { \
        uint32_t xb_ = sb + (((CH) & 1) ? O_XS1 : O_XS0); \
        uint32_t bb_ = sb + (((CH) & 1) ? O_BS1 : O_BS0); \
        _Pragma("unroll") for (int q_ = 0; q_ < 2; ++q_) { \
            int idx_ = tid + 256 * q_; int r_ = idx_ >> 4, c_ = idx_ & 15; \
            cpa16(xb_ + (r_ * XKS + c_ * 4) * 4, \
                  g_xln + (size_t)(token0 + r_) * DIMC + (CH) * 64 + c_ * 4); } \
        _Pragma("unroll") for (int q_ = 0; q_ < 7; ++q_) { \
            int idx_ = tid + 256 * q_; \
            if (idx_ < 1664) { \
                int r_ = idx_ / 26, c_ = idx_ - r_ * 26; \
                cpa16(bb_ + (r_ * BKS + c_ * 4) * 4, \
                      g_W1r + ((CH) * 64 + r_) * BKS + c_ * 4); } } \
        asm volatile("cp.async.commit_group;" ::: "memory"); \
    } while (0)

    K1B_ISSUE(0);
    K1B_ISSUE(1);

    int mt = wp >> 2, ng = wp & 3;
    int nt0 = (ng == 0) ? 0 : 4 + (ng - 1) * 3;
    int ntc = (ng == 0) ? 4 : 3;
    int g = lane >> 2, r4 = lane & 3;

    float acc[16];
    #pragma unroll
    for (int i = 0; i < 16; ++i) acc[i] = 0.f;

    uint32_t aOff = (uint32_t)(((mt * 16 + g) * XKS + r4) * 4);
    uint32_t bOff = (uint32_t)((r4 * BKS + nt0 * 8 + g) * 4);

    for (int ch = 0; ch < 8; ++ch) {
        int buf = ch & 1;
        if (ch < 7) asm volatile("cp.async.wait_group 1;" ::: "memory");
        else        asm volatile("cp.async.wait_group 0;" ::: "memory");
        __syncthreads();
        uint32_t aB = sb + (buf ? O_XS1 : O_XS0) + aOff;
        uint32_t bB = sb + (buf ? O_BS1 : O_BS0) + bOff;
        #pragma unroll
        for (int kk = 0; kk < 8; ++kk) {
            uint32_t a0 = __float_as_uint(lds_f(aB + kk * 32));
            uint32_t a1 = __float_as_uint(lds_f(aB + 8 * XKS * 4 + kk * 32));
            uint32_t a2 = __float_as_uint(lds_f(aB + kk * 32 + 16));
            uint32_t a3 = __float_as_uint(lds_f(aB + 8 * XKS * 4 + kk * 32 + 16));
            #pragma unroll
            for (int t = 0; t < 4; ++t) {
                if (t < ntc) {
                    uint32_t bb0 = __float_as_uint(lds_f(bB + kk * 8 * BKS * 4 + t * 32));
                    uint32_t bb1 = __float_as_uint(lds_f(bB + kk * 8 * BKS * 4 + 4 * BKS * 4 + t * 32));
                    MMA_TF32(&acc[t * 4], a0, a1, a2, a3, bb0, bb1);
                }
            }
        }
        __syncthreads();
        if (ch + 2 < 8) K1B_ISSUE(ch + 2);
    }

    const float is2 = 0.70710678118654752f;
    #pragma unroll
    for (int t = 0; t < 4; ++t) {
        if (t < ntc) {
            int colb = (nt0 + t) * 8 + 2 * r4;
            int row0 = mt * 16 + g;
            float v0 = acc[t * 4 + 0] + b1s[colb];
            float v1 = acc[t * 4 + 1] + b1s[colb + 1];
            float v2 = acc[t * 4 + 2] + b1s[colb];
            float v3 = acc[t * 4 + 3] + b1s[colb + 1];
            h2s[row0 * 104 + colb]       = 0.5f * v0 * (1.0f + erff(v0 * is2));
            h2s[row0 * 104 + colb + 1]   = 0.5f * v1 * (1.0f + erff(v1 * is2));
            h2s[(row0 + 8) * 104 + colb]     = 0.5f * v2 * (1.0f + erff(v2 * is2));
            h2s[(row0 + 8) * 104 + colb + 1] = 0.5f * v3 * (1.0f + erff(v3 * is2));
        }
    }
    __syncthreads();

    {
        int tok = tid >> 3, tx = tid & 7;
        float a2c[5];
        #pragma unroll
        for (int u = 0; u < 5; ++u) {
            int l = tx * 5 + u;
            a2c[u] = (l < KP) ? b2[l] : 0.f;
        }
        for (int j = 0; j < HID; ++j) {
            float hv = h2s[tok * 104 + j];
            #pragma unroll
            for (int u = 0; u < 5; ++u) a2c[u] += hv * W2s[j * 40 + tx * 5 + u];
        }
        float sc = scale[0];
        int token = token0 + tok;
        int b = token / LVTOK, ltok = token - b * LVTOK;
        #pragma unroll
        for (int u = 0; u < 5; ++u) {
            int l = tx * 5 + u;
            if (l < KP)
                g_logits[(size_t)(b * KP + l) * LVTOK + ltok] = a2c[u] * sc;
        }
    }
}

// ---------------- K234: grid-stitched (unchanged R15) ----------------
__global__ __launch_bounds__(512) void k234(const float* __restrict__ img,
                                            const float* __restrict__ cap,
                                            const int* __restrict__ cap_lens) {
    __shared__ __align__(16) float buf[KP * LVTOK];
    __shared__ float glo[DIMC];
    __shared__ float red[17];
    int tid = threadIdx.x, wid = tid >> 5, lane = tid & 31;

    if (blockIdx.x < 256) {
        int b = blockIdx.x;
        for (int k = wid; k < KP; k += 16) {
            const float* lg = g_logits + (size_t)(b * KP + k) * LVTOK;
            float m = -1e30f;
            for (int l = lane; l < LVTOK; l += 32) m = fmaxf(m, lg[l]);
            #pragma unroll
            for (int o = 16; o; o >>= 1) m = fmaxf(m, __shfl_xor_sync(0xffffffffu, m, o));
            float s = 0.f;
            for (int l = lane; l < LVTOK; l += 32) { float e = expf(lg[l] - m); buf[k * LVTOK + l] = e; s += e; }
            #pragma unroll
            for (int o = 16; o; o >>= 1) s += __shfl_xor_sync(0xffffffffu, s, o);
            float inv = 1.0f / s;
            for (int l = lane; l < LVTOK; l += 32) buf[k * LVTOK + l] *= inv;
        }
        __syncthreads();
        {
            int d = tid;
            const float* sp = img + ((size_t)b * 197 + 1) * DIMC + d;
            float acc[KP];
            #pragma unroll
            for (int k = 0; k < KP; ++k) acc[k] = 0.f;
            for (int l4 = 0; l4 < LVTOK / 4; ++l4) {
                float x0 = sp[(size_t)(l4 * 4 + 0) * DIMC];
                float x1 = sp[(size_t)(l4 * 4 + 1) * DIMC];
                float x2 = sp[(size_t)(l4 * 4 + 2) * DIMC];
                float x3 = sp[(size_t)(l4 * 4 + 3) * DIMC];
                #pragma unroll
                for (int k = 0; k < KP; ++k) {
                    float4 w = *(const float4*)(buf + k * LVTOK + l4 * 4);
                    acc[k] += w.x * x0 + w.y * x1 + w.z * x2 + w.w * x3;
                }
            }
            float* dst = g_aggr + (size_t)b * KP * DIMC + d;
            #pragma unroll
            for (int k = 0; k < KP; ++k) dst[(size_t)k * DIMC] = acc[k];
        }
        __syncthreads();

        const float* A = g_aggr + (size_t)b * KP * DIMC;
        for (int k = wid; k < KP; k += 16) {
            const float* ar = A + (size_t)k * DIMC;
            float ss = 0.f;
            for (int d = lane; d < DIMC; d += 32) { float v = ar[d]; ss += v * v; }
            #pragma unroll
            for (int o = 16; o; o >>= 1) ss += __shfl_xor_sync(0xffffffffu, ss, o);
            float n = sqrtf(ss);
            float inv = 1.0f / fmaxf(n, EPSF);
            if (lane == 0) g_r[b * KP + k] = n;
            float* dst = g_imgrows + ((size_t)b * L40 + k) * DIMC;
            __nv_bfloat16* dbf = g_imgrows_bf + ((size_t)b * L40 + k) * DIMC;
            for (int d = lane; d < DIMC; d += 32) {
                float v = ar[d] * inv;
                dst[d] = v;
                dbf[d] = __float2bfloat16(v);
            }
        }
        __syncthreads();

        {
            float s0 = 0.f;
            for (int k = 0; k < KP; ++k) s0 += A[(size_t)k * DIMC + tid];
            s0 *= (1.0f / KP);
            glo[tid] = s0;
            float p = s0 * s0;
            #pragma unroll
            for (int o = 16; o; o >>= 1) p += __shfl_xor_sync(0xffffffffu, p, o);
            if (lane == 0) red[wid] = p;
            __syncthreads();
            if (tid == 0) { float t = 0.f; for (int i = 0; i < 16; ++i) t += red[i]; red[16] = t; }
            __syncthreads();
            float invg = 1.0f / fmaxf(sqrtf(red[16]), EPSF);
            glo[tid] *= invg;
        }
        __syncthreads();

        for (int k = wid; k < KP; k += 16) {
            const float* an = g_imgrows + ((size_t)b * L40 + k) * DIMC;
            float dp = 0.f;
            for (int d = lane; d < DIMC; d += 32) dp += glo[d] * an[d];
            #pragma unroll
            for (int o = 16; o; o >>= 1) dp += __shfl_xor_sync(0xffffffffu, dp, o);
            if (lane == 0) g_attself[b * KP + k] = dp;
        }

        {
            const float* x = img + (size_t)b * 197 * DIMC;
            float v0 = x[tid];
            float p = v0 * v0;
            #pragma unroll
            for (int o = 16; o; o >>= 1) p += __shfl_xor_sync(0xffffffffu, p, o);
            __syncthreads();
            if (lane == 0) red[wid] = p;
            __syncthreads();
            if (tid == 0) { float t = 0.f; for (int i = 0; i < 16; ++i) t += red[i]; red[16] = t; }
            __syncthreads();
            float inv = 1.0f / fmaxf(sqrtf(red[16]), EPSF);
            float* dst = g_imgrows + ((size_t)b * L40 + KP) * DIMC;
            __nv_bfloat16* dbf = g_imgrows_bf + ((size_t)b * L40 + KP) * DIMC;
            dst[tid] = v0 * inv;
            dbf[tid] = __float2bfloat16(v0 * inv);
        }
        __syncthreads();

        float accG[3] = {0.f, 0.f, 0.f};
        for (int ch = 0; ch < 4; ++ch) {
            __syncthreads();
            for (int idx = tid; idx < KP * 128; idx += 512) {
                int kk = idx >> 7, dd = idx & 127;
                buf[kk * 129 + dd] = g_imgrows[((size_t)b * L40 + kk) * DIMC + ch * 128 + dd];
            }
            __syncthreads();
            int q = 0;
            for (int p = tid; p < KP * KP; p += 512, ++q) {
                int i = p / KP, j = p - i * KP;
                const float* ri = buf + i * 129;
                const float* rj = buf + j * 129;
                float s = 0.f;
                #pragma unroll 4
                for (int dd = 0; dd < 128; ++dd) s += ri[dd] * rj[dd];
                accG[q] += s;
            }
        }
        int q = 0;
        for (int p = tid; p < KP * KP; p += 512, ++q) g_G[(size_t)b * KP * KP + p] = accG[q];
    } else {
        int t = blockIdx.x - 256;
        const float* C = cap + (size_t)t * LT * DIMC;
        for (int w = wid; w < LT; w += 16) {
            const float* cw = C + (size_t)w * DIMC;
            float ss = 0.f;
            for (int d = lane; d < DIMC; d += 32) { float v = cw[d]; ss += v * v; }
            #pragma unroll
            for (int o = 16; o; o >>= 1) ss += __shfl_xor_sync(0xffffffffu, ss, o);
            float inv = 1.0f / fmaxf(sqrtf(ss), EPSF);
            __nv_bfloat16* dst = g_capn_bf + ((size_t)t * LT + w) * DIMC;
            for (int d = lane; d < DIMC; d += 32) dst[d] = __float2bfloat16(cw[d] * inv);
        }
        int nw = cap_lens[t];
        float s0 = 0.f;
        for (int w = 0; w < nw; ++w) s0 += C[(size_t)w * DIMC + tid];
        s0 *= 1.0f / (float)nw;
        float p = s0 * s0;
        #pragma unroll
        for (int o = 16; o; o >>= 1) p += __shfl_xor_sync(0xffffffffu, p, o);
        if (lane == 0) red[wid] = p;
        __syncthreads();
        if (tid == 0) { float tt = 0.f; for (int i = 0; i < 16; ++i) tt += red[i]; red[16] = tt; }
        __syncthreads();
        float inv = 1.0f / fmaxf(sqrtf(red[16]), EPSF);
        g_capglo[t * DIMC + tid] = s0 * inv;
    }
}

// ---------------- K5: 32-caption score GEMM + rank-based select (unchanged R15) ----------------
__global__ __launch_bounds__(128) void k5_merged(const int* __restrict__ cap_lens) {
    __shared__ __align__(16) float ag[32 * 36];
    __shared__ __align__(16) float an[40 * 36];
    __shared__ float scsm[32][40];
    __shared__ float ew[4][40];
    __shared__ float gsm[KP * 41];
    int b = blockIdx.x, tile = blockIdx.y;
    int tid = threadIdx.x, wid = tid >> 5, lane = tid & 31;
    int ty2 = tid >> 3, tx = tid & 7;

    {
        const float* G = g_G + (size_t)b * KP * KP;
        for (int idx = tid; idx < KP * KP; idx += 128) {
            int i = idx / KP, j = idx - i * KP;
            gsm[i * 41 + j] = G[idx];
        }
    }

    float acc0[5] = {0.f, 0.f, 0.f, 0.f, 0.f};
    float acc1[5] = {0.f, 0.f, 0.f, 0.f, 0.f};
    const float* agg = g_capglo + (size_t)tile * 32 * DIMC;
    const float* ann = g_imgrows + (size_t)b * L40 * DIMC;
    for (int dc = 0; dc < 16; ++dc) {
        __syncthreads();
        {
            #pragma unroll
            for (int qq = 0; qq < 2; ++qq) {
                int idx = tid + qq * 128;
                int r = idx >> 3, c4 = idx & 7;
                *(float4*)(ag + r * 36 + c4 * 4) =
                    *(const float4*)(agg + (size_t)r * DIMC + dc * 32 + c4 * 4);
            }
            #pragma unroll
            for (int qq = 0; qq < 3; ++qq) {
                int idx = tid + qq * 128;
                if (idx < 320) {
                    int r = idx >> 3, cc = idx & 7;
                    *(float4*)(an + r * 36 + cc * 4) =
                        *(const float4*)(ann + (size_t)r * DIMC + dc * 32 + cc * 4);
                }
            }
        }
        __syncthreads();
        #pragma unroll
        for (int dk = 0; dk < 8; ++dk) {
            float4 a4 = *(const float4*)(ag + ty2 * 36 + dk * 4);
            float4 a4b = *(const float4*)(ag + (ty2 + 16) * 36 + dk * 4);
            #pragma unroll
            for (int j = 0; j < 5; ++j) {
                float4 b4 = *(const float4*)(an + (tx * 5 + j) * 36 + dk * 4);
                acc0[j] += a4.x * b4.x + a4.y * b4.y + a4.z * b4.z + a4.w * b4.w;
                acc1[j] += a4b.x * b4.x + a4b.y * b4.y + a4b.z * b4.z + a4b.w * b4.w;
            }
        }
    }
    #pragma unroll
    for (int j = 0; j < 5; ++j) {
        int l = tx * 5 + j;
        if (l < KP) {
            float at = g_attself[b * KP + l];
            scsm[ty2][l]      = 0.8f * acc0[j] + 0.2f * at;
            scsm[ty2 + 16][l] = 0.8f * acc1[j] + 0.2f * at;
        }
    }
    __syncthreads();

    float rv0 = g_r[b * KP + lane];
    float rv1 = (lane + 32 < KP) ? g_r[b * KP + lane + 32] : 0.f;

    for (int pp = 0; pp < 8; ++pp) {
        int capi = wid * 8 + pp;
        int t = tile * 32 + capi;
        const float* sc = scsm[capi];
        float s0 = sc[lane];
        float s1 = (lane + 32 < KP) ? sc[lane + 32] : -1e30f;

        int rank0 = 0, rank1 = 0;
        int l1i = lane + 32;
        #pragma unroll 13
        for (int j = 0; j < KP; ++j) {
            float v = sc[j];
            rank0 += (v > s0 || (v == s0 && j < lane)) ? 1 : 0;
            rank1 += (v > s1 || (v == s1 && j < l1i)) ? 1 : 0;
        }
        bool sel0 = rank0 < NK;
        bool sel1 = (l1i < KP) && (rank1 < NK);
        unsigned m0 = __ballot_sync(0xffffffffu, sel0);
        unsigned m1 = __ballot_sync(0xffffffffu, sel1);
        unsigned long long mask = (unsigned long long)m0 | ((unsigned long long)m1 << 32);

        float a0 = s0 - (sel0 ? BIGNEG : 0.f);
        float a1 = (l1i < KP) ? (s1 - (sel1 ? BIGNEG : 0.f)) : -1e30f;
        float m = fmaxf(a0, a1);
        #pragma unroll
        for (int o = 16; o; o >>= 1) m = fmaxf(m, __shfl_xor_sync(0xffffffffu, m, o));
        float e0 = expf(a0 - m);
        float e1 = (l1i < KP) ? expf(a1 - m) : 0.f;
        float s = e0 + e1;
        #pragma unroll
        for (int o = 16; o; o >>= 1) s += __shfl_xor_sync(0xffffffffu, s, o);
        float invs = 1.0f / s;
        float el0 = e0 * invs * rv0;
        float el1 = (l1i < KP) ? e1 * invs * rv1 : 0.f;
        ew[wid][lane] = el0;
        if (lane < 8) ew[wid][lane + 32] = (l1i < KP) ? el1 : 0.f;
        __syncwarp();

        float ext2 = 0.f;
        const float* ewv = ew[wid];
        {
            const float* gr = gsm + lane * 41;
            float si = 0.f;
            #pragma unroll 13
            for (int j = 0; j < KP; ++j) si += gr[j] * ewv[j];
            ext2 += el0 * si;
            if (l1i < KP) {
                const float* gr2 = gsm + l1i * 41;
                float si2 = 0.f;
                #pragma unroll 13
                for (int j = 0; j < KP; ++j) si2 += gr2[j] * ewv[j];
                ext2 += el1 * si2;
            }
        }
        #pragma unroll
        for (int o = 16; o; o >>= 1) ext2 += __shfl_xor_sync(0xffffffffu, ext2, o);
        float invext = 1.0f / fmaxf(sqrtf(ext2), EPSF);
        float* cdst = g_c + ((size_t)t * BV + b) * 40;
        cdst[lane] = el0 * invext;
        if (lane < 7) cdst[lane + 32] = el1 * invext;
        if (lane == 0) {
            cdst[39] = 0.f;
            g_selmask[t * BV + b] = mask | (1ull << 39);
        }
        __syncwarp();
    }
}

// ---------------- K6: bf16 mma.sync + ldmatrix, 512 threads (occupancy 2x) ----------------
// Block = 2 captions x 4 images (unchanged). 16 warps: warp = (mh = wp>>3, img = (wp>>1)&3,
// mhalf = wp&1); each warp: 2 m16-tiles x 5 n8-tiles (40 accs) -> ~64 regs -> 2 CTAs/SM.
#define K6S 144
#define K6_A0 0
#define K6_B0 (128 * K6S)
#define K6_A1 (K6_B0 + 168 * K6S)
#define K6_B1 (K6_A1 + 128 * K6S)
#define K6_DYN (K6_B1 + 168 * K6S)

__global__ __launch_bounds__(512, 2) void k6_sim_mma(const int* __restrict__ cap_lens,
                                                     float* __restrict__ out) {
    extern __shared__ char dsm[];
    __shared__ float csh[2][4][40];
    __shared__ unsigned long long mskS[2][4];
    __shared__ float redsm[2][4][2];

    uint32_t sb = smem_u32(dsm);
    int tid = threadIdx.x, wp = tid >> 5, lane = tid & 31;
    int t0 = (blockIdx.x >> 6) * 2, b0 = (blockIdx.x & 63) * 4;
    int nw0 = cap_lens[t0], nw1 = cap_lens[t0 + 1];

    for (int i = tid; i < 320; i += 512) {
        int cap = i / 160, rest = i - cap * 160;
        int im = rest / 40, l = rest - im * 40;
        csh[cap][im][l] = g_c[((size_t)(t0 + cap) * BV + (b0 + im)) * 40 + l];
    }
    if (tid < 8) mskS[tid >> 2][tid & 3] = g_selmask[(t0 + (tid >> 2)) * BV + b0 + (tid & 3)];

#define K6_ISSUE(CH) do { \
        uint32_t ab_ = sb + (((CH) & 1) ? K6_A1 : K6_A0); \
        uint32_t bb_ = sb + (((CH) & 1) ? K6_B1 : K6_B0); \
        _Pragma("unroll") for (int q_ = 0; q_ < 2; ++q_) { \
            int idx_ = tid + 512 * q_, r_ = idx_ >> 3, c_ = idx_ & 7; \
            cpa16(ab_ + r_ * K6S + c_ * 16, \
                  g_capn_bf + ((size_t)(t0 + (r_ >> 6)) * LT + (r_ & 63)) * DIMC + (CH) * 64 + c_ * 8); } \
        _Pragma("unroll") for (int q_ = 0; q_ < 3; ++q_) { \
            int idx_ = tid + 512 * q_; \
            if (idx_ < 1280) { \
                int r_ = idx_ >> 3, c_ = idx_ & 7; \
                cpa16(bb_ + r_ * K6S + c_ * 16, \
                      g_imgrows_bf + ((size_t)(b0 + r_ / 40) * L40 + (r_ % 40)) * DIMC + (CH) * 64 + c_ * 8); } } \
        asm volatile("cp.async.commit_group;" ::: "memory"); \
    } while (0)

    K6_ISSUE(0);
    K6_ISSUE(1);

    int mh = wp >> 3, img = (wp >> 1) & 3, mhalf = wp & 1;
    int myNw = mh ? nw1 : nw0;
    // active sub-tiles for this warp: qq in {0,1} maps to m-tile (mhalf*2+qq)
    int myMq = (myNw + 15) >> 4;                  // total active m16 tiles (1..4)
    int qcnt = myMq - mhalf * 2;                   // active tiles in this warp's pair
    if (qcnt < 0) qcnt = 0;
    if (qcnt > 2) qcnt = 2;
    uint32_t aBase = (uint32_t)((mh * 64 + mhalf * 32 + (lane & 15)) * K6S + (lane >> 4) * 16);
    uint32_t bBase = (uint32_t)((img * 40 + ((lane >> 4) * 8) + (lane & 7)) * K6S
                                + ((lane >> 3) & 1) * 16);

    float acc[40];
    #pragma unroll
    for (int i = 0; i < 40; ++i) acc[i] = 0.f;

    for (int ch = 0; ch < 8; ++ch) {
        int buf = ch & 1;
        if (ch < 7) asm volatile("cp.async.wait_group 1;" ::: "memory");
        else        asm volatile("cp.async.wait_group 0;" ::: "memory");
        __syncthreads();

        uint32_t aB = sb + (buf ? K6_A1 : K6_A0) + aBase;
        uint32_t bB = sb + (buf ? K6_B1 : K6_B0) + bBase;
        #pragma unroll
        for (int kk = 0; kk < 4; ++kk) {
            uint32_t bf[12];
            #pragma unroll
            for (int p = 0; p < 3; ++p)
                ldsm_x4(bf[p * 4], bf[p * 4 + 1], bf[p * 4 + 2], bf[p * 4 + 3],
                        bB + p * (16 * K6S) + kk * 32);
            #pragma unroll
            for (int qq = 0; qq < 2; ++qq) {
                if (qq < qcnt) {
                    uint32_t a0, a1, a2, a3;
                    ldsm_x4(a0, a1, a2, a3, aB + qq * (16 * K6S) + kk * 32);
                    #pragma unroll
                    for (int nt = 0; nt < 5; ++nt)
                        MMA_BF16(&acc[qq * 20 + nt * 4], a0, a1, a2, a3, bf[nt * 2], bf[nt * 2 + 1]);
                }
            }
        }
        __syncthreads();
        if (ch + 2 < 8) K6_ISSUE(ch + 2);
    }

    int g = lane >> 2, tg = lane & 3;
    unsigned long long mask = mskS[mh][img];
    const float* cv = csh[mh][img];
    float wsum = 0.f;
    #pragma unroll
    for (int qq = 0; qq < 2; ++qq) {
        if (qq < qcnt) {
            #pragma unroll
            for (int half = 0; half < 2; ++half) {
                float smax = -1e30f, ext = 0.f;
                #pragma unroll
                for (int nt = 0; nt < 5; ++nt) {
                    #pragma unroll
                    for (int j = 0; j < 2; ++j) {
                        int l = nt * 8 + 2 * tg + j;
                        float v = acc[qq * 20 + nt * 4 + half * 2 + j];
                        if ((mask >> l) & 1ull) smax = fmaxf(smax, v);
                        ext += cv[l] * v;
                    }
                }
                smax = fmaxf(smax, __shfl_xor_sync(0xffffffffu, smax, 1));
                ext += __shfl_xor_sync(0xffffffffu, ext, 1);
                smax = fmaxf(smax, __shfl_xor_sync(0xffffffffu, smax, 2));
                ext += __shfl_xor_sync(0xffffffffu, ext, 2);
                int word = (mhalf * 2 + qq) * 16 + g + half * 8;
                if (tg == 0 && word < myNw) wsum += fmaxf(smax, ext);
            }
        }
    }
    #pragma unroll
    for (int o = 16; o; o >>= 1) wsum += __shfl_xor_sync(0xffffffffu, wsum, o);
    if (lane == 0) redsm[mh][img][mhalf] = wsum;
    __syncthreads();
    if (tid < 8) {
        int cap = tid >> 2, im = tid & 3;
        float s = redsm[cap][im][0] + redsm[cap][im][1];
        out[(size_t)(b0 + im) * BT + (t0 + cap)] = s / (float)(cap ? nw1 : nw0);
    }
}

// ---------------- launch ----------------
extern "C" void kernel_launch(void* const* d_in, const int* in_sizes, int n_in,
                              void* d_out, int out_size) {
    const float* img      = (const float*)d_in[0];
    const float* cap      = (const float*)d_in[1];
    const int*   cap_lens = (const int*)d_in[2];
    const float* lng      = (const float*)d_in[3];
    const float* lnb      = (const float*)d_in[4];
    const float* W1       = (const float*)d_in[5];
    const float* b1       = (const float*)d_in[6];
    const float* W2       = (const float*)d_in[7];
    const float* b2       = (const float*)d_in[8];
    const float* scale    = (const float*)d_in[9];
    float* out = (float*)d_out;

    cudaFuncSetAttribute(k1b_mlp, cudaFuncAttributeMaxDynamicSharedMemorySize, K1B_DYN);
    cudaFuncSetAttribute(k6_sim_mma, cudaFuncAttributeMaxDynamicSharedMemorySize, K6_DYN);

    k1a_ln<<<6272 + 52, 256>>>(img, lng, lnb, W1);
    k1b_mlp<<<(BV * LVTOK) / 32, 256, K1B_DYN>>>(W2, b1, b2, scale);
    k234<<<512, 512>>>(img, cap, cap_lens);
    dim3 g5(BV, BT / 32);
    k5_merged<<<g5, 128>>>(cap_lens);
    k6_sim_mma<<<(BT / 2) * (BV / 4), 512, K6_DYN>>>(cap_lens, out);
}

// round 17
// speedup vs baseline: 1.0815x; 1.0815x over previous
#include <cuda_runtime.h>
#include <cuda_bf16.h>
#include <math.h>
#include <stdint.h>

#define BV 256
#define LVTOK 196
#define BT 256
#define LT 64
#define DIMC 512
#define HID 102
#define KP 39
#define NK 19
#define L40 40
#define EPSF 1e-12f
#define BIGNEG 1e10f

// ---------------- static device scratch (no allocations) ----------------
__device__ float g_xln[(size_t)BV * LVTOK * DIMC];
__device__ float g_W1r[512 * 104];
__device__ float g_logits[BV * KP * LVTOK];
__device__ float g_aggr[(size_t)BV * KP * DIMC];
__device__ float g_imgrows[(size_t)BV * L40 * DIMC];
__device__ __nv_bfloat16 g_imgrows_bf[(size_t)BV * L40 * DIMC];
__device__ __nv_bfloat16 g_capn_bf[(size_t)BT * LT * DIMC];
__device__ float g_r[BV * KP];
__device__ float g_attself[BV * KP];
__device__ float g_G[(size_t)BV * KP * KP];
__device__ float g_capglo[BT * DIMC];
__device__ float g_c[(size_t)BT * BV * 40];
__device__ unsigned long long g_selmask[BT * BV];

// ---------------- helpers ----------------
__device__ __forceinline__ uint32_t smem_u32(const void* p) {
    uint32_t a;
    asm("{ .reg .u64 t; cvta.to.shared.u64 t, %1; cvt.u32.u64 %0, t; }" : "=r"(a) : "l"(p));
    return a;
}
__device__ __forceinline__ void cpa16(uint32_t dst, const void* src) {
    asm volatile("cp.async.cg.shared.global [%0], [%1], 16;" :: "r"(dst), "l"(src));
}
__device__ __forceinline__ void ldsm_x4(uint32_t& r0, uint32_t& r1, uint32_t& r2, uint32_t& r3,
                                        uint32_t addr) {
    asm volatile("ldmatrix.sync.aligned.m8n8.x4.shared.b16 {%0,%1,%2,%3}, [%4];"
                 : "=r"(r0), "=r"(r1), "=r"(r2), "=r"(r3) : "r"(addr));
}
__device__ __forceinline__ float lds_f(uint32_t addr) {
    float v;
    asm volatile("ld.shared.f32 %0, [%1];" : "=f"(v) : "r"(addr));
    return v;
}
__device__ __forceinline__ float f2tf32(float x) {
    uint32_t o;
    asm("cvt.rna.tf32.f32 %0, %1;" : "=r"(o) : "f"(x));
    return __uint_as_float(o);
}
#define MMA_BF16(C, A0, A1, A2, A3, B0, B1) \
    asm volatile("mma.sync.aligned.m16n8k16.row.col.f32.bf16.bf16.f32 " \
        "{%0,%1,%2,%3}, {%4,%5,%6,%7}, {%8,%9}, {%0,%1,%2,%3};" \
        : "+f"((C)[0]), "+f"((C)[1]), "+f"((C)[2]), "+f"((C)[3]) \
        : "r"(A0), "r"(A1), "r"(A2), "r"(A3), "r"(B0), "r"(B1))
#define MMA_TF32(C, A0, A1, A2, A3, B0, B1) \
    asm volatile("mma.sync.aligned.m16n8k8.row.col.f32.tf32.tf32.f32 " \
        "{%0,%1,%2,%3}, {%4,%5,%6,%7}, {%8,%9}, {%0,%1,%2,%3};" \
        : "+f"((C)[0]), "+f"((C)[1]), "+f"((C)[2]), "+f"((C)[3]) \
        : "r"(A0), "r"(A1), "r"(A2), "r"(A3), "r"(B0), "r"(B1))

// ---------------- K1a: LN -> g_xln (tf32) + W1 prep [unchanged] ----------------
__global__ __launch_bounds__(256) void k1a_ln(const float* __restrict__ img,
                                              const float* __restrict__ lng,
                                              const float* __restrict__ lnb,
                                              const float* __restrict__ W1) {
    if (blockIdx.x < 6272) {
        __shared__ __align__(16) float gsh[DIMC], bsh[DIMC];
        int tid = threadIdx.x, wid = tid >> 5, lane = tid & 31;
        for (int d = tid; d < DIMC; d += 256) { gsh[d] = lng[d]; bsh[d] = lnb[d]; }
        __syncthreads();
        int token = blockIdx.x * 8 + wid;
        int b = token / LVTOK, l = token - b * LVTOK;
        const float4* x4 = (const float4*)(img + ((size_t)(b * 197) + 1 + l) * DIMC);
        float4 xv[4]; float s = 0.f, ss = 0.f;
        #pragma unroll
        for (int e = 0; e < 4; ++e) {
            float4 v = x4[lane + 32 * e]; xv[e] = v;
            s += v.x + v.y + v.z + v.w;
            ss += v.x * v.x + v.y * v.y + v.z * v.z + v.w * v.w;
        }
        #pragma unroll
        for (int o = 16; o; o >>= 1) {
            s  += __shfl_xor_sync(0xffffffffu, s, o);
            ss += __shfl_xor_sync(0xffffffffu, ss, o);
        }
        float mu = s * (1.0f / DIMC);
        float rstd = rsqrtf(ss * (1.0f / DIMC) - mu * mu + 1e-5f);
        float4* xd = (float4*)(g_xln + (size_t)token * DIMC);
        #pragma unroll
        for (int e = 0; e < 4; ++e) {
            int i4 = lane + 32 * e;
            float4 g4 = ((const float4*)gsh)[i4];
            float4 b4 = ((const float4*)bsh)[i4];
            float4 o4;
            o4.x = f2tf32((xv[e].x - mu) * rstd * g4.x + b4.x);
            o4.y = f2tf32((xv[e].y - mu) * rstd * g4.y + b4.y);
            o4.z = f2tf32((xv[e].z - mu) * rstd * g4.z + b4.z);
            o4.w = f2tf32((xv[e].w - mu) * rstd * g4.w + b4.w);
            xd[i4] = o4;
        }
    } else {
        int base = (blockIdx.x - 6272) * 1024 + threadIdx.x * 4;
        #pragma unroll
        for (int u = 0; u < 4; ++u) {
            int idx = base + u;
            if (idx < 512 * 104) {
                int k = idx / 104, n = idx - k * 104;
                g_W1r[idx] = (n < HID) ? f2tf32(W1[k * HID + n]) : 0.f;
            }
        }
    }
}

// ---------------- K1b: tf32 mma GEMM1 + gelu + fp32 GEMM2 -> logits [unchanged] ----------------
#define XKS 68
#define BKS 104
#define XS_BYTES (32 * XKS * 4)
#define BS_BYTES (64 * BKS * 4)
#define O_XS0 0
#define O_XS1 (O_XS0 + XS_BYTES)
#define O_BS0 (O_XS1 + XS_BYTES)
#define O_BS1 (O_BS0 + BS_BYTES)
#define O_H2  (O_BS1 + BS_BYTES)
#define O_W2  (O_H2 + 32 * 104 * 4)
#define O_B1  (O_W2 + HID * 40 * 4)
#define K1B_DYN (O_B1 + 104 * 4)

__global__ __launch_bounds__(256) void k1b_mlp(const float* __restrict__ W2,
                                               const float* __restrict__ b1,
                                               const float* __restrict__ b2,
                                               const float* __restrict__ scale) {
    extern __shared__ char dsm[];
    uint32_t sb = smem_u32(dsm);
    float* h2s = (float*)(dsm + O_H2);
    float* W2s = (float*)(dsm + O_W2);
    float* b1s = (float*)(dsm + O_B1);
    int tid = threadIdx.x, wp = tid >> 5, lane = tid & 31;
    int token0 = blockIdx.x * 32;

    for (int idx = tid; idx < HID * KP; idx += 256) {
        int j = idx / KP, l = idx - j * KP;
        W2s[j * 40 + l] = W2[idx];
    }
    if (tid < 104) b1s[tid] = (tid < HID) ? b1[tid] : 0.f;

#define K1B_ISSUE(CH) do { \
        uint32_t xb_ = sb + (((CH) & 1) ? O_XS1 : O_XS0); \
        uint32_t bb_ = sb + (((CH) & 1) ? O_BS1 : O_BS0); \
        _Pragma("unroll") for (int q_ = 0; q_ < 2; ++q_) { \
            int idx_ = tid + 256 * q_; int r_ = idx_ >> 4, c_ = idx_ & 15; \
            cpa16(xb_ + (r_ * XKS + c_ * 4) * 4, \
                  g_xln + (size_t)(token0 + r_) * DIMC + (CH) * 64 + c_ * 4); } \
        _Pragma("unroll") for (int q_ = 0; q_ < 7; ++q_) { \
            int idx_ = tid + 256 * q_; \
            if (idx_ < 1664) { \
                int r_ = idx_ / 26, c_ = idx_ - r_ * 26; \
                cpa16(bb_ + (r_ * BKS + c_ * 4) * 4, \
                      g_W1r + ((CH) * 64 + r_) * BKS + c_ * 4); } } \
        asm volatile("cp.async.commit_group;" ::: "memory"); \
    } while (0)

    K1B_ISSUE(0);
    K1B_ISSUE(1);

    int mt = wp >> 2, ng = wp & 3;
    int nt0 = (ng == 0) ? 0 : 4 + (ng - 1) * 3;
    int ntc = (ng == 0) ? 4 : 3;
    int g = lane >> 2, r4 = lane & 3;

    float acc[16];
    #pragma unroll
    for (int i = 0; i < 16; ++i) acc[i] = 0.f;

    uint32_t aOff = (uint32_t)(((mt * 16 + g) * XKS + r4) * 4);
    uint32_t bOff = (uint32_t)((r4 * BKS + nt0 * 8 + g) * 4);

    for (int ch = 0; ch < 8; ++ch) {
        int buf = ch & 1;
        if (ch < 7) asm volatile("cp.async.wait_group 1;" ::: "memory");
        else        asm volatile("cp.async.wait_group 0;" ::: "memory");
        __syncthreads();
        uint32_t aB = sb + (buf ? O_XS1 : O_XS0) + aOff;
        uint32_t bB = sb + (buf ? O_BS1 : O_BS0) + bOff;
        #pragma unroll
        for (int kk = 0; kk < 8; ++kk) {
            uint32_t a0 = __float_as_uint(lds_f(aB + kk * 32));
            uint32_t a1 = __float_as_uint(lds_f(aB + 8 * XKS * 4 + kk * 32));
            uint32_t a2 = __float_as_uint(lds_f(aB + kk * 32 + 16));
            uint32_t a3 = __float_as_uint(lds_f(aB + 8 * XKS * 4 + kk * 32 + 16));
            #pragma unroll
            for (int t = 0; t < 4; ++t) {
                if (t < ntc) {
                    uint32_t bb0 = __float_as_uint(lds_f(bB + kk * 8 * BKS * 4 + t * 32));
                    uint32_t bb1 = __float_as_uint(lds_f(bB + kk * 8 * BKS * 4 + 4 * BKS * 4 + t * 32));
                    MMA_TF32(&acc[t * 4], a0, a1, a2, a3, bb0, bb1);
                }
            }
        }
        __syncthreads();
        if (ch + 2 < 8) K1B_ISSUE(ch + 2);
    }

    const float is2 = 0.70710678118654752f;
    #pragma unroll
    for (int t = 0; t < 4; ++t) {
        if (t < ntc) {
            int colb = (nt0 + t) * 8 + 2 * r4;
            int row0 = mt * 16 + g;
            float v0 = acc[t * 4 + 0] + b1s[colb];
            float v1 = acc[t * 4 + 1] + b1s[colb + 1];
            float v2 = acc[t * 4 + 2] + b1s[colb];
            float v3 = acc[t * 4 + 3] + b1s[colb + 1];
            h2s[row0 * 104 + colb]       = 0.5f * v0 * (1.0f + erff(v0 * is2));
            h2s[row0 * 104 + colb + 1]   = 0.5f * v1 * (1.0f + erff(v1 * is2));
            h2s[(row0 + 8) * 104 + colb]     = 0.5f * v2 * (1.0f + erff(v2 * is2));
            h2s[(row0 + 8) * 104 + colb + 1] = 0.5f * v3 * (1.0f + erff(v3 * is2));
        }
    }
    __syncthreads();

    {
        int tok = tid >> 3, tx = tid & 7;
        float a2c[5];
        #pragma unroll
        for (int u = 0; u < 5; ++u) {
            int l = tx * 5 + u;
            a2c[u] = (l < KP) ? b2[l] : 0.f;
        }
        for (int j = 0; j < HID; ++j) {
            float hv = h2s[tok * 104 + j];
            #pragma unroll
            for (int u = 0; u < 5; ++u) a2c[u] += hv * W2s[j * 40 + tx * 5 + u];
        }
        float sc = scale[0];
        int token = token0 + tok;
        int b = token / LVTOK, ltok = token - b * LVTOK;
        #pragma unroll
        for (int u = 0; u < 5; ++u) {
            int l = tx * 5 + u;
            if (l < KP)
                g_logits[(size_t)(b * KP + l) * LVTOK + ltok] = a2c[u] * sc;
        }
    }
}

// ---------------- K234: grid-stitched (unchanged R15) ----------------
__global__ __launch_bounds__(512) void k234(const float* __restrict__ img,
                                            const float* __restrict__ cap,
                                            const int* __restrict__ cap_lens) {
    __shared__ __align__(16) float buf[KP * LVTOK];
    __shared__ float glo[DIMC];
    __shared__ float red[17];
    int tid = threadIdx.x, wid = tid >> 5, lane = tid & 31;

    if (blockIdx.x < 256) {
        int b = blockIdx.x;
        for (int k = wid; k < KP; k += 16) {
            const float* lg = g_logits + (size_t)(b * KP + k) * LVTOK;
            float m = -1e30f;
            for (int l = lane; l < LVTOK; l += 32) m = fmaxf(m, lg[l]);
            #pragma unroll
            for (int o = 16; o; o >>= 1) m = fmaxf(m, __shfl_xor_sync(0xffffffffu, m, o));
            float s = 0.f;
            for (int l = lane; l < LVTOK; l += 32) { float e = expf(lg[l] - m); buf[k * LVTOK + l] = e; s += e; }
            #pragma unroll
            for (int o = 16; o; o >>= 1) s += __shfl_xor_sync(0xffffffffu, s, o);
            float inv = 1.0f / s;
            for (int l = lane; l < LVTOK; l += 32) buf[k * LVTOK + l] *= inv;
        }
        __syncthreads();
        {
            int d = tid;
            const float* sp = img + ((size_t)b * 197 + 1) * DIMC + d;
            float acc[KP];
            #pragma unroll
            for (int k = 0; k < KP; ++k) acc[k] = 0.f;
            for (int l4 = 0; l4 < LVTOK / 4; ++l4) {
                float x0 = sp[(size_t)(l4 * 4 + 0) * DIMC];
                float x1 = sp[(size_t)(l4 * 4 + 1) * DIMC];
                float x2 = sp[(size_t)(l4 * 4 + 2) * DIMC];
                float x3 = sp[(size_t)(l4 * 4 + 3) * DIMC];
                #pragma unroll
                for (int k = 0; k < KP; ++k) {
                    float4 w = *(const float4*)(buf + k * LVTOK + l4 * 4);
                    acc[k] += w.x * x0 + w.y * x1 + w.z * x2 + w.w * x3;
                }
            }
            float* dst = g_aggr + (size_t)b * KP * DIMC + d;
            #pragma unroll
            for (int k = 0; k < KP; ++k) dst[(size_t)k * DIMC] = acc[k];
        }
        __syncthreads();

        const float* A = g_aggr + (size_t)b * KP * DIMC;
        for (int k = wid; k < KP; k += 16) {
            const float* ar = A + (size_t)k * DIMC;
            float ss = 0.f;
            for (int d = lane; d < DIMC; d += 32) { float v = ar[d]; ss += v * v; }
            #pragma unroll
            for (int o = 16; o; o >>= 1) ss += __shfl_xor_sync(0xffffffffu, ss, o);
            float n = sqrtf(ss);
            float inv = 1.0f / fmaxf(n, EPSF);
            if (lane == 0) g_r[b * KP + k] = n;
            float* dst = g_imgrows + ((size_t)b * L40 + k) * DIMC;
            __nv_bfloat16* dbf = g_imgrows_bf + ((size_t)b * L40 + k) * DIMC;
            for (int d = lane; d < DIMC; d += 32) {
                float v = ar[d] * inv;
                dst[d] = v;
                dbf[d] = __float2bfloat16(v);
            }
        }
        __syncthreads();

        {
            float s0 = 0.f;
            for (int k = 0; k < KP; ++k) s0 += A[(size_t)k * DIMC + tid];
            s0 *= (1.0f / KP);
            glo[tid] = s0;
            float p = s0 * s0;
            #pragma unroll
            for (int o = 16; o; o >>= 1) p += __shfl_xor_sync(0xffffffffu, p, o);
            if (lane == 0) red[wid] = p;
            __syncthreads();
            if (tid == 0) { float t = 0.f; for (int i = 0; i < 16; ++i) t += red[i]; red[16] = t; }
            __syncthreads();
            float invg = 1.0f / fmaxf(sqrtf(red[16]), EPSF);
            glo[tid] *= invg;
        }
        __syncthreads();

        for (int k = wid; k < KP; k += 16) {
            const float* an = g_imgrows + ((size_t)b * L40 + k) * DIMC;
            float dp = 0.f;
            for (int d = lane; d < DIMC; d += 32) dp += glo[d] * an[d];
            #pragma unroll
            for (int o = 16; o; o >>= 1) dp += __shfl_xor_sync(0xffffffffu, dp, o);
            if (lane == 0) g_attself[b * KP + k] = dp;
        }

        {
            const float* x = img + (size_t)b * 197 * DIMC;
            float v0 = x[tid];
            float p = v0 * v0;
            #pragma unroll
            for (int o = 16; o; o >>= 1) p += __shfl_xor_sync(0xffffffffu, p, o);
            __syncthreads();
            if (lane == 0) red[wid] = p;
            __syncthreads();
            if (tid == 0) { float t = 0.f; for (int i = 0; i < 16; ++i) t += red[i]; red[16] = t; }
            __syncthreads();
            float inv = 1.0f / fmaxf(sqrtf(red[16]), EPSF);
            float* dst = g_imgrows + ((size_t)b * L40 + KP) * DIMC;
            __nv_bfloat16* dbf = g_imgrows_bf + ((size_t)b * L40 + KP) * DIMC;
            dst[tid] = v0 * inv;
            dbf[tid] = __float2bfloat16(v0 * inv);
        }
        __syncthreads();

        float accG[3] = {0.f, 0.f, 0.f};
        for (int ch = 0; ch < 4; ++ch) {
            __syncthreads();
            for (int idx = tid; idx < KP * 128; idx += 512) {
                int kk = idx >> 7, dd = idx & 127;
                buf[kk * 129 + dd] = g_imgrows[((size_t)b * L40 + kk) * DIMC + ch * 128 + dd];
            }
            __syncthreads();
            int q = 0;
            for (int p = tid; p < KP * KP; p += 512, ++q) {
                int i = p / KP, j = p - i * KP;
                const float* ri = buf + i * 129;
                const float* rj = buf + j * 129;
                float s = 0.f;
                #pragma unroll 4
                for (int dd = 0; dd < 128; ++dd) s += ri[dd] * rj[dd];
                accG[q] += s;
            }
        }
        int q = 0;
        for (int p = tid; p < KP * KP; p += 512, ++q) g_G[(size_t)b * KP * KP + p] = accG[q];
    } else {
        int t = blockIdx.x - 256;
        const float* C = cap + (size_t)t * LT * DIMC;
        for (int w = wid; w < LT; w += 16) {
            const float* cw = C + (size_t)w * DIMC;
            float ss = 0.f;
            for (int d = lane; d < DIMC; d += 32) { float v = cw[d]; ss += v * v; }
            #pragma unroll
            for (int o = 16; o; o >>= 1) ss += __shfl_xor_sync(0xffffffffu, ss, o);
            float inv = 1.0f / fmaxf(sqrtf(ss), EPSF);
            __nv_bfloat16* dst = g_capn_bf + ((size_t)t * LT + w) * DIMC;
            for (int d = lane; d < DIMC; d += 32) dst[d] = __float2bfloat16(cw[d] * inv);
        }
        int nw = cap_lens[t];
        float s0 = 0.f;
        for (int w = 0; w < nw; ++w) s0 += C[(size_t)w * DIMC + tid];
        s0 *= 1.0f / (float)nw;
        float p = s0 * s0;
        #pragma unroll
        for (int o = 16; o; o >>= 1) p += __shfl_xor_sync(0xffffffffu, p, o);
        if (lane == 0) red[wid] = p;
        __syncthreads();
        if (tid == 0) { float tt = 0.f; for (int i = 0; i < 16; ++i) tt += red[i]; red[16] = tt; }
        __syncthreads();
        float inv = 1.0f / fmaxf(sqrtf(red[16]), EPSF);
        g_capglo[t * DIMC + tid] = s0 * inv;
    }
}

// ---------------- K5: 64-caption score GEMM (4x5 register tile) + rank-based select ----------------
__global__ __launch_bounds__(128) void k5_merged(const int* __restrict__ cap_lens) {
    __shared__ __align__(16) float ag[64 * 36];
    __shared__ __align__(16) float an[40 * 36];
    __shared__ float scsm[64][40];
    __shared__ float ew[4][40];
    __shared__ float gsm[KP * 41];
    int b = blockIdx.x, tile = blockIdx.y;
    int tid = threadIdx.x, wid = tid >> 5, lane = tid & 31;
    int ty2 = tid >> 3, tx = tid & 7;    // ty2: 0..15 -> captions ty2, +16, +32, +48

    {
        const float* G = g_G + (size_t)b * KP * KP;
        for (int idx = tid; idx < KP * KP; idx += 128) {
            int i = idx / KP, j = idx - i * KP;
            gsm[i * 41 + j] = G[idx];
        }
    }

    float acc[4][5];
    #pragma unroll
    for (int c = 0; c < 4; ++c)
        #pragma unroll
        for (int j = 0; j < 5; ++j) acc[c][j] = 0.f;
    const float* agg = g_capglo + (size_t)tile * 64 * DIMC;
    const float* ann = g_imgrows + (size_t)b * L40 * DIMC;
    for (int dc = 0; dc < 16; ++dc) {
        __syncthreads();
        {
            // ag: 64 rows x 32 floats = 512 float4
            #pragma unroll
            for (int qq = 0; qq < 4; ++qq) {
                int idx = tid + qq * 128;
                int r = idx >> 3, c4 = idx & 7;
                *(float4*)(ag + r * 36 + c4 * 4) =
                    *(const float4*)(agg + (size_t)r * DIMC + dc * 32 + c4 * 4);
            }
            // an: 40 rows x 32 floats = 320 float4
            #pragma unroll
            for (int qq = 0; qq < 3; ++qq) {
                int idx = tid + qq * 128;
                if (idx < 320) {
                    int r = idx >> 3, cc = idx & 7;
                    *(float4*)(an + r * 36 + cc * 4) =
                        *(const float4*)(ann + (size_t)r * DIMC + dc * 32 + cc * 4);
                }
            }
        }
        __syncthreads();
        #pragma unroll
        for (int dk = 0; dk < 8; ++dk) {
            float4 a4[4];
            #pragma unroll
            for (int c = 0; c < 4; ++c)
                a4[c] = *(const float4*)(ag + (ty2 + c * 16) * 36 + dk * 4);
            #pragma unroll
            for (int j = 0; j < 5; ++j) {
                float4 b4 = *(const float4*)(an + (tx * 5 + j) * 36 + dk * 4);
                #pragma unroll
                for (int c = 0; c < 4; ++c)
                    acc[c][j] += a4[c].x * b4.x + a4[c].y * b4.y + a4[c].z * b4.z + a4[c].w * b4.w;
            }
        }
    }
    #pragma unroll
    for (int j = 0; j < 5; ++j) {
        int l = tx * 5 + j;
        if (l < KP) {
            float at = g_attself[b * KP + l];
            #pragma unroll
            for (int c = 0; c < 4; ++c)
                scsm[ty2 + c * 16][l] = 0.8f * acc[c][j] + 0.2f * at;
        }
    }
    __syncthreads();

    float rv0 = g_r[b * KP + lane];
    float rv1 = (lane + 32 < KP) ? g_r[b * KP + lane + 32] : 0.f;

    for (int pp = 0; pp < 16; ++pp) {
        int capi = wid * 16 + pp;
        int t = tile * 64 + capi;
        const float* sc = scsm[capi];
        float s0 = sc[lane];
        float s1 = (lane + 32 < KP) ? sc[lane + 32] : -1e30f;

        int rank0 = 0, rank1 = 0;
        int l1i = lane + 32;
        #pragma unroll 13
        for (int j = 0; j < KP; ++j) {
            float v = sc[j];
            rank0 += (v > s0 || (v == s0 && j < lane)) ? 1 : 0;
            rank1 += (v > s1 || (v == s1 && j < l1i)) ? 1 : 0;
        }
        bool sel0 = rank0 < NK;
        bool sel1 = (l1i < KP) && (rank1 < NK);
        unsigned m0 = __ballot_sync(0xffffffffu, sel0);
        unsigned m1 = __ballot_sync(0xffffffffu, sel1);
        unsigned long long mask = (unsigned long long)m0 | ((unsigned long long)m1 << 32);

        float a0 = s0 - (sel0 ? BIGNEG : 0.f);
        float a1 = (l1i < KP) ? (s1 - (sel1 ? BIGNEG : 0.f)) : -1e30f;
        float m = fmaxf(a0, a1);
        #pragma unroll
        for (int o = 16; o; o >>= 1) m = fmaxf(m, __shfl_xor_sync(0xffffffffu, m, o));
        float e0 = expf(a0 - m);
        float e1 = (l1i < KP) ? expf(a1 - m) : 0.f;
        float s = e0 + e1;
        #pragma unroll
        for (int o = 16; o; o >>= 1) s += __shfl_xor_sync(0xffffffffu, s, o);
        float invs = 1.0f / s;
        float el0 = e0 * invs * rv0;
        float el1 = (l1i < KP) ? e1 * invs * rv1 : 0.f;
        ew[wid][lane] = el0;
        if (lane < 8) ew[wid][lane + 32] = (l1i < KP) ? el1 : 0.f;
        __syncwarp();

        float ext2 = 0.f;
        const float* ewv = ew[wid];
        {
            const float* gr = gsm + lane * 41;
            float si = 0.f;
            #pragma unroll 13
            for (int j = 0; j < KP; ++j) si += gr[j] * ewv[j];
            ext2 += el0 * si;
            if (l1i < KP) {
                const float* gr2 = gsm + l1i * 41;
                float si2 = 0.f;
                #pragma unroll 13
                for (int j = 0; j < KP; ++j) si2 += gr2[j] * ewv[j];
                ext2 += el1 * si2;
            }
        }
        #pragma unroll
        for (int o = 16; o; o >>= 1) ext2 += __shfl_xor_sync(0xffffffffu, ext2, o);
        float invext = 1.0f / fmaxf(sqrtf(ext2), EPSF);
        float* cdst = g_c + ((size_t)t * BV + b) * 40;
        cdst[lane] = el0 * invext;
        if (lane < 7) cdst[lane + 32] = el1 * invext;
        if (lane == 0) {
            cdst[39] = 0.f;
            g_selmask[t * BV + b] = mask | (1ull << 39);
        }
        __syncwarp();
    }
}

// ---------------- K6: bf16 mma.sync + ldmatrix GEMM (reverted to R15 256-thread) ----------------
#define K6S 144
#define K6_A0 0
#define K6_B0 (128 * K6S)
#define K6_A1 (K6_B0 + 168 * K6S)
#define K6_B1 (K6_A1 + 128 * K6S)
#define K6_DYN (K6_B1 + 168 * K6S)

__global__ __launch_bounds__(256, 2) void k6_sim_mma(const int* __restrict__ cap_lens,
                                                     float* __restrict__ out) {
    extern __shared__ char dsm[];
    __shared__ float csh[2][4][40];
    __shared__ unsigned long long mskS[2][4];
    __shared__ float redsm[2][4];

    uint32_t sb = smem_u32(dsm);
    int tid = threadIdx.x, wp = tid >> 5, lane = tid & 31;
    int t0 = (blockIdx.x >> 6) * 2, b0 = (blockIdx.x & 63) * 4;
    int nw0 = cap_lens[t0], nw1 = cap_lens[t0 + 1];

    for (int i = tid; i < 320; i += 256) {
        int cap = i / 160, rest = i - cap * 160;
        int im = rest / 40, l = rest - im * 40;
        csh[cap][im][l] = g_c[((size_t)(t0 + cap) * BV + (b0 + im)) * 40 + l];
    }
    if (tid < 8) mskS[tid >> 2][tid & 3] = g_selmask[(t0 + (tid >> 2)) * BV + b0 + (tid & 3)];

#define K6_ISSUE(CH) do { \
        uint32_t ab_ = sb + (((CH) & 1) ? K6_A1 : K6_A0); \
        uint32_t bb_ = sb + (((CH) & 1) ? K6_B1 : K6_B0); \
        _Pragma("unroll") for (int q_ = 0; q_ < 4; ++q_) { \
            int idx_ = tid + 256 * q_, r_ = idx_ >> 3, c_ = idx_ & 7; \
            cpa16(ab_ + r_ * K6S + c_ * 16, \
                  g_capn_bf + ((size_t)(t0 + (r_ >> 6)) * LT + (r_ & 63)) * DIMC + (CH) * 64 + c_ * 8); } \
        _Pragma("unroll") for (int q_ = 0; q_ < 5; ++q_) { \
            int idx_ = tid + 256 * q_, r_ = idx_ >> 3, c_ = idx_ & 7; \
            cpa16(bb_ + r_ * K6S + c_ * 16, \
                  g_imgrows_bf + ((size_t)(b0 + r_ / 40) * L40 + (r_ % 40)) * DIMC + (CH) * 64 + c_ * 8); } \
        asm volatile("cp.async.commit_group;" ::: "memory"); \
    } while (0)

    K6_ISSUE(0);
    K6_ISSUE(1);

    int mh = wp >> 2, img = wp & 3;
    int myNw = mh ? nw1 : nw0;
    int myMq = (myNw + 15) >> 4;
    uint32_t aBase = (uint32_t)((mh * 64 + (lane & 15)) * K6S + (lane >> 4) * 16);
    uint32_t bBase = (uint32_t)((img * 40 + ((lane >> 4) * 8) + (lane & 7)) * K6S
                                + ((lane >> 3) & 1) * 16);

    float acc[80];
    #pragma unroll
    for (int i = 0; i < 80; ++i) acc[i] = 0.f;

    for (int ch = 0; ch < 8; ++ch) {
        int buf = ch & 1;
        if (ch < 7) asm volatile("cp.async.wait_group 1;" ::: "memory");
        else        asm volatile("cp.async.wait_group 0;" ::: "memory");
        __syncthreads();

        uint32_t aB = sb + (buf ? K6_A1 : K6_A0) + aBase;
        uint32_t bB = sb + (buf ? K6_B1 : K6_B0) + bBase;
        #pragma unroll
        for (int kk = 0; kk < 4; ++kk) {
            uint32_t bf[12];
            #pragma unroll
            for (int p = 0; p < 3; ++p)
                ldsm_x4(bf[p * 4], bf[p * 4 + 1], bf[p * 4 + 2], bf[p * 4 + 3],
                        bB + p * (16 * K6S) + kk * 32);
            #pragma unroll
            for (int q = 0; q < 4; ++q) {
                if (q < myMq) {
                    uint32_t a0, a1, a2, a3;
                    ldsm_x4(a0, a1, a2, a3, aB + q * (16 * K6S) + kk * 32);
                    #pragma unroll
                    for (int nt = 0; nt < 5; ++nt)
                        MMA_BF16(&acc[q * 20 + nt * 4], a0, a1, a2, a3, bf[nt * 2], bf[nt * 2 + 1]);
                }
            }
        }
        __syncthreads();
        if (ch + 2 < 8) K6_ISSUE(ch + 2);
    }

    int g = lane >> 2, tg = lane & 3;
    unsigned long long mask = mskS[mh][img];
    const float* cv = csh[mh][img];
    float wsum = 0.f;
    #pragma unroll
    for (int q = 0; q < 4; ++q) {
        if (q < myMq) {
            #pragma unroll
            for (int half = 0; half < 2; ++half) {
                float smax = -1e30f, ext = 0.f;
                #pragma unroll
                for (int nt = 0; nt < 5; ++nt) {
                    #pragma unroll
                    for (int j = 0; j < 2; ++j) {
                        int l = nt * 8 + 2 * tg + j;
                        float v = acc[q * 20 + nt * 4 + half * 2 + j];
                        if ((mask >> l) & 1ull) smax = fmaxf(smax, v);
                        ext += cv[l] * v;
                    }
                }
                smax = fmaxf(smax, __shfl_xor_sync(0xffffffffu, smax, 1));
                ext += __shfl_xor_sync(0xffffffffu, ext, 1);
                smax = fmaxf(smax, __shfl_xor_sync(0xffffffffu, smax, 2));
                ext += __shfl_xor_sync(0xffffffffu, ext, 2);
                int word = q * 16 + g + half * 8;
                if (tg == 0 && word < myNw) wsum += fmaxf(smax, ext);
            }
        }
    }
    #pragma unroll
    for (int o = 16; o; o >>= 1) wsum += __shfl_xor_sync(0xffffffffu, wsum, o);
    if (lane == 0) redsm[mh][img] = wsum;
    __syncthreads();
    if (tid < 8) {
        int cap = tid >> 2, im = tid & 3;
        out[(size_t)(b0 + im) * BT + (t0 + cap)] = redsm[cap][im] / (float)(cap ? nw1 : nw0);
    }
}

// ---------------- launch ----------------
extern "C" void kernel_launch(void* const* d_in, const int* in_sizes, int n_in,
                              void* d_out, int out_size) {
    const float* img      = (const float*)d_in[0];
    const float* cap      = (const float*)d_in[1];
    const int*   cap_lens = (const int*)d_in[2];
    const float* lng      = (const float*)d_in[3];
    const float* lnb      = (const float*)d_in[4];
    const float* W1       = (const float*)d_in[5];
    const float* b1       = (const float*)d_in[6];
    const float* W2       = (const float*)d_in[7];
    const float* b2       = (const float*)d_in[8];
    const float* scale    = (const float*)d_in[9];
    float* out = (float*)d_out;

    cudaFuncSetAttribute(k1b_mlp, cudaFuncAttributeMaxDynamicSharedMemorySize, K1B_DYN);
    cudaFuncSetAttribute(k6_sim_mma, cudaFuncAttributeMaxDynamicSharedMemorySize, K6_DYN);

    k1a_ln<<<6272 + 52, 256>>>(img, lng, lnb, W1);
    k1b_mlp<<<(BV * LVTOK) / 32, 256, K1B_DYN>>>(W2, b1, b2, scale);
    k234<<<512, 512>>>(img, cap, cap_lens);
    dim3 g5(BV, BT / 64);
    k5_merged<<<g5, 128>>>(cap_lens);
    k6_sim_mma<<<(BT / 2) * (BV / 4), 256, K6_DYN>>>(cap_lens, out);
}